// round 15
// baseline (speedup 1.0000x reference)
#include <cuda_runtime.h>
#include <math.h>

#define B_MAX 65536
#define EPSV 1e-5f

// ---------------- scratch (device globals; no allocations) ----------------
__device__ float4 g_xd4[B_MAX * 18];            // downscaled rows 0..7 (72 floats/sample)
__device__ float  g_w2eff[45 * 15 * 25];        // BN-folded expert conv weights
__device__ float  g_b2eff[45 * 15];             // BN-folded expert conv bias
__device__ int    g_cnt[46];                    // zero-init; self-resetting each run
__device__ int    g_off[46];
__device__ int    g_total;
__device__ int    g_done;
__device__ unsigned char  g_eid[B_MAX];
__device__ unsigned char  g_t2[B_MAX];          // idx0 | idx1<<4
__device__ int    g_order[B_MAX];

// ---------------- k_fused1: downscale + conv1 + pool + fc1 + top2 ---------
// block = 128 samples. Stages raw x through smem in 8-sample chunks
// (coalesced), downscales rows 0..7 only, then computes stage1 from smem.
// Dynamic smem: sxd (128*73 floats) + sx (8*672 floats, later aliased
// by sfwt+slog).
__global__ void __launch_bounds__(128)
k_fused1(const float* __restrict__ x,
         const float* __restrict__ w1, const float* __restrict__ b1,
         const float* __restrict__ g1, const float* __restrict__ be1,
         const float* __restrict__ m1, const float* __restrict__ v1,
         const float* __restrict__ fcw1, const float* __restrict__ fcb1,
         float* __restrict__ out1, float* __restrict__ out2, int B) {
    extern __shared__ __align__(16) float dsm[];
    float* sxd  = dsm;            // 9344 floats, stride 73/sample (conflict-free)
    float* sx   = dsm + 9344;     // 5376 floats (8 samples x 672)
    float* sfwt = sx;             // alias: 2160 floats, fc1 transposed [f][c], pad 12
    float* slog = sx + 2160;      // alias: 1280 floats, logits staging

    __shared__ float sw1[180];
    __shared__ float sb1[20];
    __shared__ float sfb[10];
    __shared__ float ssc[20];
    __shared__ int   shist[45];
    __shared__ int   scnt2[45];
    __shared__ int   sticket;

    int tid = threadIdx.x;
    int s0 = blockIdx.x * 128;

    if (tid < 20) {
        float sv = g1[tid] * rsqrtf(v1[tid] + EPSV);
        ssc[tid] = sv;
        sb1[tid] = b1[tid] * sv + be1[tid] - m1[tid] * sv;
    }
    if (tid < 10) sfb[tid] = fcb1[tid];
    if (tid < 45) shist[tid] = 0;
    __syncthreads();
    for (int i = tid; i < 180; i += 128) sw1[i] = w1[i] * ssc[i / 9];

    // ---- 16 chunks of 8 samples: coalesced load + downscale ----
    for (int c = 0; c < 16; c++) {
        int cs = s0 + c * 8;
        int ns = min(8, B - cs);
        if (ns > 0) {
            // load first 24 rows (168 float4) per sample, coalesced
            const float4* xp = (const float4*)(x + (size_t)cs * 784);
            float4* sp = (float4*)sx;
            int n4 = ns * 168;
            for (int i = tid; i < n4; i += 128) {
                int si = i / 168, j = i - si * 168;
                sp[si * 168 + j] = __ldg(xp + si * 196 + j);
            }
        }
        __syncthreads();
        if (ns > 0) {
            int tot = ns * 72;
            for (int o = tid; o < tot; o += 128) {
                int sl = o / 72, p = o - sl * 72;
                int orr = p / 9, occ = p - orr * 9;
                const float* base = sx + sl * 672 + orr * 84 + occ * 3;
                float acc = base[0]  + base[1]  + base[2]
                          + base[28] + base[29] + base[30]
                          + base[56] + base[57] + base[58];
                sxd[(c * 8 + sl) * 73 + p] = acc * (1.f / 9.f);
            }
        }
        __syncthreads();
    }

    // ---- write g_xd4 (stride 72 floats), fully coalesced ----
    {
        int nvalid = min(128, B - s0);
        if (nvalid > 0) {
            float* gx = (float*)g_xd4 + (size_t)s0 * 72;
            int tot = nvalid * 72;
            for (int i = tid; i < tot; i += 128) {
                int sl = i / 72, p = i - sl * 72;
                gx[i] = sxd[sl * 73 + p];
            }
        }
    }

    // ---- load fc1 weights into alias region (sx no longer needed) ----
    for (int i = tid; i < 2160; i += 128) {
        int f = i / 12, cc = i - f * 12;
        sfwt[i] = (cc < 10) ? fcw1[cc * 180 + f] : 0.f;
    }
    __syncthreads();

    // ---- per-thread stage1 compute (R10 structure) ----
    int s = s0 + tid;
    int my_e = -1;

    if (s < B) {
        float xd[72];
        #pragma unroll
        for (int k = 0; k < 72; k++) xd[k] = sxd[tid * 73 + k];

        float logits[10];
        #pragma unroll
        for (int c = 0; c < 10; c++) logits[c] = sfb[c];

        for (int oc = 0; oc < 20; oc++) {
            float w[9];
            #pragma unroll
            for (int k = 0; k < 9; k++) w[k] = sw1[oc * 9 + k];
            float bb = sb1[oc];
            #pragma unroll
            for (int pr = 0; pr < 3; pr++) {
                #pragma unroll
                for (int pc = 0; pc < 3; pc++) {
                    float m = 0.f;   // relu floor
                    #pragma unroll
                    for (int dr = 0; dr < 2; dr++) {
                        #pragma unroll
                        for (int dc = 0; dc < 2; dc++) {
                            int r = 2 * pr + dr, c0 = 2 * pc + dc;
                            float acc = bb;
                            #pragma unroll
                            for (int kr = 0; kr < 3; kr++)
                                #pragma unroll
                                for (int kc = 0; kc < 3; kc++)
                                    acc = fmaf(xd[(r + kr) * 9 + (c0 + kc)], w[kr * 3 + kc], acc);
                            m = fmaxf(m, acc);
                        }
                    }
                    int f = oc * 9 + pr * 3 + pc;
                    const float4* wp = (const float4*)(sfwt + f * 12);
                    float4 A = wp[0], Bq = wp[1], C = wp[2];
                    logits[0] = fmaf(m, A.x,  logits[0]);
                    logits[1] = fmaf(m, A.y,  logits[1]);
                    logits[2] = fmaf(m, A.z,  logits[2]);
                    logits[3] = fmaf(m, A.w,  logits[3]);
                    logits[4] = fmaf(m, Bq.x, logits[4]);
                    logits[5] = fmaf(m, Bq.y, logits[5]);
                    logits[6] = fmaf(m, Bq.z, logits[6]);
                    logits[7] = fmaf(m, Bq.w, logits[7]);
                    logits[8] = fmaf(m, C.x,  logits[8]);
                    logits[9] = fmaf(m, C.y,  logits[9]);
                }
            }
        }

        #pragma unroll
        for (int c = 0; c < 10; c++) slog[tid * 10 + c] = logits[c];

        float mx = logits[0];
        #pragma unroll
        for (int c = 1; c < 10; c++) mx = fmaxf(mx, logits[c]);
        float se = 0.f;
        #pragma unroll
        for (int c = 0; c < 10; c++) se += expf(logits[c] - mx);
        float lse = logf(se);

        int i1 = 0; float b1v = logits[0];
        #pragma unroll
        for (int c = 1; c < 10; c++) if (logits[c] >= b1v) { b1v = logits[c]; i1 = c; }
        int i2 = -1; float b2v = -3.4e38f;
        #pragma unroll
        for (int c = 0; c < 10; c++) if (c != i1 && logits[c] >= b2v) { b2v = logits[c]; i2 = c; }

        int idx0 = min(i1, i2), idx1 = max(i1, i2);
        int eid = idx0 * 9 - (idx0 * (idx0 - 1)) / 2 + (idx1 - idx0 - 1);

        bool use1 = (-lse) > 0.3f;
        if (use1) {
            float* o = out2 + (size_t)s * 10;
            #pragma unroll
            for (int c = 0; c < 10; c++) o[c] = logits[c] - mx - lse;
            g_eid[s] = 45;
        } else {
            g_eid[s] = (unsigned char)eid;
            g_t2[s]  = (unsigned char)(idx0 | (idx1 << 4));
            my_e = eid;
        }
    }

    // block-aggregated expert count
    if (my_e >= 0) atomicAdd(&shist[my_e], 1);
    __syncthreads();
    if (tid < 45 && shist[tid] > 0) atomicAdd(&g_cnt[tid], shist[tid]);

    // coalesced out1 write
    {
        int nvalid = min(128, B - s0);
        if (nvalid == 128) {
            float4* op = (float4*)(out1 + (size_t)blockIdx.x * 1280);
            const float4* sp = (const float4*)slog;
            for (int i = tid; i < 320; i += 128) op[i] = sp[i];
        } else if (nvalid > 0) {
            float* op = out1 + (size_t)blockIdx.x * 1280;
            for (int i = tid; i < nvalid * 10; i += 128) op[i] = slog[i];
        }
    }

    // fused offsets: last block computes prefix, then self-resets counters
    __threadfence();
    if (tid == 0) sticket = atomicAdd(&g_done, 1);
    __syncthreads();
    if (sticket == (int)gridDim.x - 1) {
        if (tid < 45) scnt2[tid] = atomicAdd(&g_cnt[tid], 0);
        __syncthreads();
        if (tid < 46) g_cnt[tid] = 0;       // reset for next graph replay
        if (tid == 0) {
            int acc = 0;
            for (int e = 0; e < 45; e++) { g_off[e] = acc; acc += scnt2[e]; }
            g_total = acc;
            g_done = 0;
        }
    }
}

// ---------------- k_scatter2: bucket sort + fused expert BN-fold ----------
__global__ void __launch_bounds__(512)
k_scatter2(int B,
           const float* __restrict__ w2, const float* __restrict__ b2,
           const float* __restrict__ g2, const float* __restrict__ be2,
           const float* __restrict__ m2, const float* __restrict__ v2) {
    __shared__ int shist[45];
    __shared__ int sbase[45];
    __shared__ float sc[15];
    int tid = threadIdx.x;

    if (blockIdx.x < 45 && tid < 15) {
        int e = blockIdx.x;
        float sv = g2[e * 15 + tid] * rsqrtf(v2[e * 15 + tid] + EPSV);
        sc[tid] = sv;
        g_b2eff[e * 15 + tid] = b2[e * 15 + tid] * sv + be2[e * 15 + tid] - m2[e * 15 + tid] * sv;
    }
    if (tid < 45) shist[tid] = 0;
    __syncthreads();
    if (blockIdx.x < 45) {
        int e = blockIdx.x;
        for (int k = tid; k < 375; k += 512)
            g_w2eff[e * 375 + k] = w2[e * 375 + k] * sc[k / 25];
    }

    int s = blockIdx.x * 512 + tid;
    int e = 46, r = 0;
    if (s < B) {
        e = g_eid[s];
        if (e < 45) r = atomicAdd(&shist[e], 1);
    }
    __syncthreads();
    if (tid < 45 && shist[tid] > 0) sbase[tid] = atomicAdd(&g_off[tid], shist[tid]);
    __syncthreads();
    if (e < 45) g_order[sbase[e] + r] = s;
}

// ---------------- k_stage2: R10 structure, 18-float4 input ----------------
__global__ void __launch_bounds__(128)
k_stage2(const float* __restrict__ fcw2, const float* __restrict__ fcb2,
         float* __restrict__ out2, int B) {
    int i = blockIdx.x * 128 + threadIdx.x;
    if (i >= g_total) return;
    int s = g_order[i];
    int e = g_eid[s];

    float xd[72];
    {
        const float4* xi = &g_xd4[(size_t)s * 18];
        #pragma unroll
        for (int j = 0; j < 18; j++) {
            float4 q = __ldg(xi + j);
            xd[4 * j] = q.x; xd[4 * j + 1] = q.y; xd[4 * j + 2] = q.z; xd[4 * j + 3] = q.w;
        }
    }

    const float* W  = g_w2eff + e * 375;
    const float* Be = g_b2eff + e * 15;
    float s20 = __ldg(fcb2 + e * 2 + 0);
    float s21 = __ldg(fcb2 + e * 2 + 1);

    for (int o = 0; o < 15; o++) {
        float w[25];
        #pragma unroll
        for (int k = 0; k < 25; k++) w[k] = __ldg(W + o * 25 + k);
        float bb = __ldg(Be + o);
        #pragma unroll
        for (int pp = 0; pp < 2; pp++) {
            #pragma unroll
            for (int qq = 0; qq < 2; qq++) {
                float m = 0.f;
                #pragma unroll
                for (int dr = 0; dr < 2; dr++) {
                    #pragma unroll
                    for (int dc = 0; dc < 2; dc++) {
                        int r = 2 * pp + dr, c0 = 2 * qq + dc;
                        float acc = bb;
                        #pragma unroll
                        for (int i5 = 0; i5 < 5; i5++)
                            #pragma unroll
                            for (int j5 = 0; j5 < 5; j5++)
                                acc = fmaf(xd[(r + i5) * 9 + (c0 + j5)], w[i5 * 5 + j5], acc);
                        m = fmaxf(m, acc);
                    }
                }
                int f = o * 4 + pp * 2 + qq;
                s20 = fmaf(m, __ldg(fcw2 + (size_t)(e * 2 + 0) * 60 + f), s20);
                s21 = fmaf(m, __ldg(fcw2 + (size_t)(e * 2 + 1) * 60 + f), s21);
            }
        }
    }

    unsigned t2 = g_t2[s];
    int idx0 = t2 & 15, idx1 = t2 >> 4;
    float row[10];
    #pragma unroll
    for (int c = 0; c < 10; c++) row[c] = -100.f;
    row[idx0] = s20; row[idx1] = s21;
    float mx = row[0];
    #pragma unroll
    for (int c = 1; c < 10; c++) mx = fmaxf(mx, row[c]);
    float se = 0.f;
    #pragma unroll
    for (int c = 0; c < 10; c++) se += expf(row[c] - mx);
    float lse = logf(se);
    float* o = out2 + (size_t)s * 10;
    #pragma unroll
    for (int c = 0; c < 10; c++) o[c] = row[c] - mx - lse;
}

// ---------------- launch --------------------------------------------------
extern "C" void kernel_launch(void* const* d_in, const int* in_sizes, int n_in,
                              void* d_out, int out_size) {
    const float* x    = (const float*)d_in[0];
    const float* w1   = (const float*)d_in[1];
    const float* b1   = (const float*)d_in[2];
    const float* g1   = (const float*)d_in[3];
    const float* be1  = (const float*)d_in[4];
    const float* m1   = (const float*)d_in[5];
    const float* v1   = (const float*)d_in[6];
    const float* fcw1 = (const float*)d_in[7];
    const float* fcb1 = (const float*)d_in[8];
    const float* w2   = (const float*)d_in[9];
    const float* b2   = (const float*)d_in[10];
    const float* g2   = (const float*)d_in[11];
    const float* be2  = (const float*)d_in[12];
    const float* m2   = (const float*)d_in[13];
    const float* v2   = (const float*)d_in[14];
    const float* fcw2 = (const float*)d_in[15];
    const float* fcb2 = (const float*)d_in[16];

    int B = in_sizes[0] / 784;
    if (B > B_MAX) B = B_MAX;

    float* out1 = (float*)d_out;
    float* out2 = out1 + (size_t)B * 10;

    const int DSM_BYTES = (9344 + 5376) * 4;   // 58880 B dynamic smem
    static int attr_set = 0;
    if (!attr_set) {
        cudaFuncSetAttribute(k_fused1, cudaFuncAttributeMaxDynamicSharedMemorySize, DSM_BYTES);
        attr_set = 1;
    }

    k_fused1<<<(B + 127) / 128, 128, DSM_BYTES>>>(x, w1, b1, g1, be1, m1, v1, fcw1, fcb1, out1, out2, B);
    k_scatter2<<<(B + 511) / 512, 512>>>(B, w2, b2, g2, be2, m2, v2);
    k_stage2<<<(B + 127) / 128, 128>>>(fcw2, fcb2, out2, B);
}

// round 16
// speedup vs baseline: 1.4678x; 1.4678x over previous
#include <cuda_runtime.h>
#include <math.h>

#define B_MAX 65536
#define EPSV 1e-5f
#define DS_S 16    // samples per downscale block

// ---------------- scratch (device globals; no allocations) ----------------
__device__ float4 g_xd4[B_MAX * 18];            // downscaled rows 0..7 (72 floats/sample)
__device__ float  g_w2eff[45 * 15 * 25];        // BN-folded expert conv weights
__device__ float  g_b2eff[45 * 15];             // BN-folded expert conv bias
__device__ int    g_cnt[46];
__device__ int    g_off[46];
__device__ int    g_total;
__device__ int    g_done;
__device__ unsigned char  g_eid[B_MAX];
__device__ unsigned char  g_t2[B_MAX];          // idx0 | idx1<<4
__device__ int    g_order[B_MAX];

// ---------------- k_down2: coalesced downscale (rows 0..7) + BN-fold prep -
__global__ void __launch_bounds__(256)
k_down2(const float* __restrict__ x, int B,
        const float* __restrict__ w2, const float* __restrict__ b2,
        const float* __restrict__ g2, const float* __restrict__ be2,
        const float* __restrict__ m2, const float* __restrict__ v2) {
    __shared__ __align__(16) float sx[DS_S * 672];   // rows 0..23 only
    __shared__ __align__(16) float sxd[DS_S * 72];
    __shared__ float sc[15];

    int tid = threadIdx.x;

    if (blockIdx.x < 45) {
        int e = blockIdx.x;
        if (tid < 15) {
            float s = g2[e * 15 + tid] * rsqrtf(v2[e * 15 + tid] + EPSV);
            sc[tid] = s;
            g_b2eff[e * 15 + tid] = b2[e * 15 + tid] * s + be2[e * 15 + tid] - m2[e * 15 + tid] * s;
        }
    }
    if (blockIdx.x == 0) {
        if (tid < 46) g_cnt[tid] = 0;
        if (tid == 64) g_done = 0;
    }
    __syncthreads();
    if (blockIdx.x < 45) {
        int e = blockIdx.x;
        for (int k = tid; k < 375; k += 256)
            g_w2eff[e * 375 + k] = w2[e * 375 + k] * sc[k / 25];
    }

    int s0 = blockIdx.x * DS_S;
    int ns = min(DS_S, B - s0);

    // load first 24 rows (168 float4) per sample, coalesced
    {
        const float4* xp = (const float4*)(x + (size_t)s0 * 784);
        float4* sp = (float4*)sx;
        int n4 = ns * 168;
        for (int i = tid; i < n4; i += 256) {
            int si = i / 168, j = i - si * 168;
            sp[si * 168 + j] = __ldg(xp + si * 196 + j);
        }
    }
    __syncthreads();

    // 72 means per sample (output rows 0..7)
    for (int o = tid; o < ns * 72; o += 256) {
        int sl = o / 72, p = o - sl * 72;
        int orr = p / 9, occ = p - orr * 9;
        const float* base = sx + sl * 672 + orr * 84 + occ * 3;
        float acc = base[0]  + base[1]  + base[2]
                  + base[28] + base[29] + base[30]
                  + base[56] + base[57] + base[58];
        sxd[sl * 72 + p] = acc * (1.f / 9.f);
    }
    __syncthreads();

    // coalesced store (18 float4 per sample)
    {
        float4* gp = (float4*)&g_xd4[(size_t)s0 * 18];
        const float4* sq = (const float4*)sxd;
        int n4 = ns * 18;
        for (int i = tid; i < n4; i += 256) gp[i] = sq[i];
    }
}

// ---------------- k_stage1c: conv1 + pool + fc1 + top2 + fused offsets ----
__global__ void __launch_bounds__(128)
k_stage1c(const float* __restrict__ w1, const float* __restrict__ b1,
          const float* __restrict__ g1, const float* __restrict__ be1,
          const float* __restrict__ m1, const float* __restrict__ v1,
          const float* __restrict__ fcw1, const float* __restrict__ fcb1,
          float* __restrict__ out1, float* __restrict__ out2, int B) {
    __shared__ __align__(16) float slog[128 * 10];
    __shared__ __align__(16) float sfwt[180 * 12];
    __shared__ float sw1[180];
    __shared__ float sb1[20];
    __shared__ float sfb[10];
    __shared__ float ssc[20];
    __shared__ int   shist[45];
    __shared__ int   scnt2[45];
    __shared__ int   sticket;

    int tid = threadIdx.x;
    if (tid < 20) {
        float s = g1[tid] * rsqrtf(v1[tid] + EPSV);
        ssc[tid] = s;
        sb1[tid] = b1[tid] * s + be1[tid] - m1[tid] * s;
    }
    if (tid < 10) sfb[tid] = fcb1[tid];
    if (tid < 45) shist[tid] = 0;
    __syncthreads();
    for (int i = tid; i < 180; i += 128) sw1[i] = w1[i] * ssc[i / 9];
    for (int i = tid; i < 180 * 12; i += 128) {
        int f = i / 12, c = i - f * 12;
        sfwt[i] = (c < 10) ? fcw1[c * 180 + f] : 0.f;
    }
    __syncthreads();

    int s = blockIdx.x * 128 + tid;
    int my_e = -1;

    if (s < B) {
        float xd[72];
        {
            const float4* xi = &g_xd4[(size_t)s * 18];
            #pragma unroll
            for (int j = 0; j < 18; j++) {
                float4 q = __ldg(xi + j);
                xd[4 * j] = q.x; xd[4 * j + 1] = q.y; xd[4 * j + 2] = q.z; xd[4 * j + 3] = q.w;
            }
        }

        float logits[10];
        #pragma unroll
        for (int c = 0; c < 10; c++) logits[c] = sfb[c];

        for (int oc = 0; oc < 20; oc++) {
            float w[9];
            #pragma unroll
            for (int k = 0; k < 9; k++) w[k] = sw1[oc * 9 + k];
            float bb = sb1[oc];
            #pragma unroll
            for (int pr = 0; pr < 3; pr++) {
                #pragma unroll
                for (int pc = 0; pc < 3; pc++) {
                    float m = 0.f;
                    #pragma unroll
                    for (int dr = 0; dr < 2; dr++) {
                        #pragma unroll
                        for (int dc = 0; dc < 2; dc++) {
                            int r = 2 * pr + dr, c0 = 2 * pc + dc;
                            float acc = bb;
                            #pragma unroll
                            for (int kr = 0; kr < 3; kr++)
                                #pragma unroll
                                for (int kc = 0; kc < 3; kc++)
                                    acc = fmaf(xd[(r + kr) * 9 + (c0 + kc)], w[kr * 3 + kc], acc);
                            m = fmaxf(m, acc);
                        }
                    }
                    int f = oc * 9 + pr * 3 + pc;
                    const float4* wp = (const float4*)(sfwt + f * 12);
                    float4 A = wp[0], Bq = wp[1], C = wp[2];
                    logits[0] = fmaf(m, A.x,  logits[0]);
                    logits[1] = fmaf(m, A.y,  logits[1]);
                    logits[2] = fmaf(m, A.z,  logits[2]);
                    logits[3] = fmaf(m, A.w,  logits[3]);
                    logits[4] = fmaf(m, Bq.x, logits[4]);
                    logits[5] = fmaf(m, Bq.y, logits[5]);
                    logits[6] = fmaf(m, Bq.z, logits[6]);
                    logits[7] = fmaf(m, Bq.w, logits[7]);
                    logits[8] = fmaf(m, C.x,  logits[8]);
                    logits[9] = fmaf(m, C.y,  logits[9]);
                }
            }
        }

        #pragma unroll
        for (int c = 0; c < 10; c++) slog[tid * 10 + c] = logits[c];

        float mx = logits[0];
        #pragma unroll
        for (int c = 1; c < 10; c++) mx = fmaxf(mx, logits[c]);
        float se = 0.f;
        #pragma unroll
        for (int c = 0; c < 10; c++) se += expf(logits[c] - mx);
        float lse = logf(se);

        int i1 = 0; float b1v = logits[0];
        #pragma unroll
        for (int c = 1; c < 10; c++) if (logits[c] >= b1v) { b1v = logits[c]; i1 = c; }
        int i2 = -1; float b2v = -3.4e38f;
        #pragma unroll
        for (int c = 0; c < 10; c++) if (c != i1 && logits[c] >= b2v) { b2v = logits[c]; i2 = c; }

        int idx0 = min(i1, i2), idx1 = max(i1, i2);
        int eid = idx0 * 9 - (idx0 * (idx0 - 1)) / 2 + (idx1 - idx0 - 1);

        bool use1 = (-lse) > 0.3f;
        if (use1) {
            float* o = out2 + (size_t)s * 10;
            #pragma unroll
            for (int c = 0; c < 10; c++) o[c] = logits[c] - mx - lse;
            g_eid[s] = 45;
        } else {
            g_eid[s] = (unsigned char)eid;
            g_t2[s]  = (unsigned char)(idx0 | (idx1 << 4));
            my_e = eid;
        }
    }

    if (my_e >= 0) atomicAdd(&shist[my_e], 1);
    __syncthreads();
    if (tid < 45 && shist[tid] > 0) atomicAdd(&g_cnt[tid], shist[tid]);

    {
        int nvalid = min(128, B - blockIdx.x * 128);
        if (nvalid == 128) {
            float4* op = (float4*)(out1 + (size_t)blockIdx.x * 1280);
            const float4* sp = (const float4*)slog;
            for (int i = tid; i < 320; i += 128) op[i] = sp[i];
        } else if (nvalid > 0) {
            float* op = out1 + (size_t)blockIdx.x * 1280;
            for (int i = tid; i < nvalid * 10; i += 128) op[i] = slog[i];
        }
    }

    // fused offsets: last block computes the 45-bucket prefix
    __threadfence();
    if (tid == 0) sticket = atomicAdd(&g_done, 1);
    __syncthreads();
    if (sticket == (int)gridDim.x - 1) {
        if (tid < 45) scnt2[tid] = atomicAdd(&g_cnt[tid], 0);
        __syncthreads();
        if (tid == 0) {
            int acc = 0;
            for (int e = 0; e < 45; e++) { g_off[e] = acc; acc += scnt2[e]; }
            g_total = acc;
            g_done = 0;   // reset for next graph replay
        }
    }
}

// ---------------- k_scatter: block-aggregated bucket sort -----------------
__global__ void __launch_bounds__(512)
k_scatter(int B) {
    __shared__ int shist[45];
    __shared__ int sbase[45];
    int tid = threadIdx.x;
    if (tid < 45) shist[tid] = 0;
    __syncthreads();

    int s = blockIdx.x * 512 + tid;
    int e = 46, r = 0;
    if (s < B) {
        e = g_eid[s];
        if (e < 45) r = atomicAdd(&shist[e], 1);
    }
    __syncthreads();
    if (tid < 45 && shist[tid] > 0) sbase[tid] = atomicAdd(&g_off[tid], shist[tid]);
    __syncthreads();
    if (e < 45) g_order[sbase[e] + r] = s;
}

// ---------------- k_stage2: R10 structure (flat, sorted, broadcast LDGs) --
__global__ void __launch_bounds__(128)
k_stage2(const float* __restrict__ fcw2, const float* __restrict__ fcb2,
         float* __restrict__ out2, int B) {
    int i = blockIdx.x * 128 + threadIdx.x;
    if (i >= g_total) return;
    int s = g_order[i];
    int e = g_eid[s];

    float xd[72];
    {
        const float4* xi = &g_xd4[(size_t)s * 18];
        #pragma unroll
        for (int j = 0; j < 18; j++) {
            float4 q = __ldg(xi + j);
            xd[4 * j] = q.x; xd[4 * j + 1] = q.y; xd[4 * j + 2] = q.z; xd[4 * j + 3] = q.w;
        }
    }

    const float* W  = g_w2eff + e * 375;
    const float* Be = g_b2eff + e * 15;
    float s20 = __ldg(fcb2 + e * 2 + 0);
    float s21 = __ldg(fcb2 + e * 2 + 1);

    for (int o = 0; o < 15; o++) {
        float w[25];
        #pragma unroll
        for (int k = 0; k < 25; k++) w[k] = __ldg(W + o * 25 + k);
        float bb = __ldg(Be + o);
        #pragma unroll
        for (int pp = 0; pp < 2; pp++) {
            #pragma unroll
            for (int qq = 0; qq < 2; qq++) {
                float m = 0.f;
                #pragma unroll
                for (int dr = 0; dr < 2; dr++) {
                    #pragma unroll
                    for (int dc = 0; dc < 2; dc++) {
                        int r = 2 * pp + dr, c0 = 2 * qq + dc;
                        float acc = bb;
                        #pragma unroll
                        for (int i5 = 0; i5 < 5; i5++)
                            #pragma unroll
                            for (int j5 = 0; j5 < 5; j5++)
                                acc = fmaf(xd[(r + i5) * 9 + (c0 + j5)], w[i5 * 5 + j5], acc);
                        m = fmaxf(m, acc);
                    }
                }
                int f = o * 4 + pp * 2 + qq;
                s20 = fmaf(m, __ldg(fcw2 + (size_t)(e * 2 + 0) * 60 + f), s20);
                s21 = fmaf(m, __ldg(fcw2 + (size_t)(e * 2 + 1) * 60 + f), s21);
            }
        }
    }

    unsigned t2 = g_t2[s];
    int idx0 = t2 & 15, idx1 = t2 >> 4;
    float row[10];
    #pragma unroll
    for (int c = 0; c < 10; c++) row[c] = -100.f;
    row[idx0] = s20; row[idx1] = s21;
    float mx = row[0];
    #pragma unroll
    for (int c = 1; c < 10; c++) mx = fmaxf(mx, row[c]);
    float se = 0.f;
    #pragma unroll
    for (int c = 0; c < 10; c++) se += expf(row[c] - mx);
    float lse = logf(se);
    float* o = out2 + (size_t)s * 10;
    #pragma unroll
    for (int c = 0; c < 10; c++) o[c] = row[c] - mx - lse;
}

// ---------------- launch --------------------------------------------------
extern "C" void kernel_launch(void* const* d_in, const int* in_sizes, int n_in,
                              void* d_out, int out_size) {
    const float* x    = (const float*)d_in[0];
    const float* w1   = (const float*)d_in[1];
    const float* b1   = (const float*)d_in[2];
    const float* g1   = (const float*)d_in[3];
    const float* be1  = (const float*)d_in[4];
    const float* m1   = (const float*)d_in[5];
    const float* v1   = (const float*)d_in[6];
    const float* fcw1 = (const float*)d_in[7];
    const float* fcb1 = (const float*)d_in[8];
    const float* w2   = (const float*)d_in[9];
    const float* b2   = (const float*)d_in[10];
    const float* g2   = (const float*)d_in[11];
    const float* be2  = (const float*)d_in[12];
    const float* m2   = (const float*)d_in[13];
    const float* v2   = (const float*)d_in[14];
    const float* fcw2 = (const float*)d_in[15];
    const float* fcb2 = (const float*)d_in[16];

    int B = in_sizes[0] / 784;
    if (B > B_MAX) B = B_MAX;

    float* out1 = (float*)d_out;
    float* out2 = out1 + (size_t)B * 10;

    k_down2<<<(B + DS_S - 1) / DS_S, 256>>>(x, B, w2, b2, g2, be2, m2, v2);
    k_stage1c<<<(B + 127) / 128, 128>>>(w1, b1, g1, be1, m1, v1, fcw1, fcb1, out1, out2, B);
    k_scatter<<<(B + 511) / 512, 512>>>(B);
    k_stage2<<<(B + 127) / 128, 128>>>(fcw2, fcb2, out2, B);
}